// round 10
// baseline (speedup 1.0000x reference)
#include <cuda_runtime.h>
#include <cuda_bf16.h>
#include <cstdint>

// Problem shape
#define NB   256
#define NH   512
#define NW   512
#define HW   (NH * NW)          // 262144 = 1<<18
#define NTOT ((size_t)NB * HW)  // 67108864
#define BPB  4                  // blocks per batch
#define NBLK (NB * BPB)         // 1024
#define CHUNK (HW / BPB)        // 65536 elems per block (256KB/array)
#define STAGE_ELEMS 1024        // elems per stage (4KB/array, 16B/thread)
#define STAGES (CHUNK / STAGE_ELEMS)  // 64
#define DEPTH 4                 // pipeline depth (smem ring)
#define FWHM 0.5f
#define DHW  32                 // h/H_SCALE = w/W_SCALE = 512/16

// Scratch (no allocations allowed — __device__ globals, zeroed at load)
__device__ unsigned long long g_keyblk[NBLK];  // per-block argmax key
__device__ double   g_part1[NBLK];             // per-block unweighted sqdiff sum
__device__ double   g_part2[NB];               // per-batch window correction
__device__ unsigned g_bdone[NB];               // per-batch ticket (self-resetting)
__device__ unsigned g_done;                    // global ticket  (self-resetting)

__device__ __forceinline__ void cp16(uint32_t saddr, const float* gptr) {
    asm volatile("cp.async.cg.shared.global [%0], [%1], 16;"
                 :: "r"(saddr), "l"(gptr) : "memory");
}
__device__ __forceinline__ void cp_commit() {
    asm volatile("cp.async.commit_group;" ::: "memory");
}
template <int N>
__device__ __forceinline__ void cp_wait() {
    asm volatile("cp.async.wait_group %0;" :: "n"(N) : "memory");
}

// max of a float4
__device__ __forceinline__ float vmax4(float4 v) {
    return fmaxf(fmaxf(v.x, v.y), fmaxf(v.z, v.w));
}
// first index (0..3) within float4 equal to m
__device__ __forceinline__ unsigned vpick4(float4 v, float m) {
    return (v.x == m) ? 0u : (v.y == m) ? 1u : (v.z == m) ? 2u : 3u;
}

// ---------------------------------------------------------------------------
// ONE fused kernel:
//  phase A: cp.async (LDGSTS) 4-deep smem pipeline. Each thread async-copies
//     its own 16B/array/stage and consumes only its own bytes after
//     wait_group -> no __syncthreads in the streaming loop. In-flight bytes
//     per SM ~100KB (vs ~30KB register-batched), hiding full DRAM latency.
//     Accumulate unweighted sum((o-t)^2) + per-block first-argmax of target.
//     key = (float_bits << 32) | (0xFFFFFFFF - idx): target in [0,1) so uint
//     order == float order; larger ~idx under max => first-max tie-break.
//  phase B (last block of each batch): <=64x64 ramp-window correction.
//  phase C (globally last block): deterministic sum of all partials -> mean.
// ---------------------------------------------------------------------------
__global__ __launch_bounds__(256)
void fused_kernel(const float* __restrict__ outp, const float* __restrict__ tgtp,
                  float* __restrict__ res) {
    __shared__ alignas(16) float4 sbuf[DEPTH][2][256];   // 32KB ring

    const int batch = blockIdx.x >> 2;        // / BPB
    const int chunk = blockIdx.x & (BPB - 1);
    const size_t base = (size_t)batch * HW + (size_t)chunk * CHUNK;
    const float* __restrict__ tg = tgtp + base;
    const float* __restrict__ og = outp + base;
    const unsigned idx0 = (unsigned)(chunk * CHUNK);
    const int tid = threadIdx.x;

    // per-thread smem slot addresses (shared-space u32)
    uint32_t st_addr[DEPTH], so_addr[DEPTH];
    #pragma unroll
    for (int d = 0; d < DEPTH; d++) {
        st_addr[d] = (uint32_t)__cvta_generic_to_shared(&sbuf[d][0][tid]);
        so_addr[d] = (uint32_t)__cvta_generic_to_shared(&sbuf[d][1][tid]);
    }
    const int toff = tid * 4;                 // this thread's elem offset in stage

    // ---------------- phase A: async-pipelined streaming ----------------
    // prologue: fill the ring
    #pragma unroll
    for (int d = 0; d < DEPTH; d++) {
        cp16(st_addr[d], tg + d * STAGE_ELEMS + toff);
        cp16(so_addr[d], og + d * STAGE_ELEMS + toff);
        cp_commit();
    }

    float s0 = 0.0f, s1 = 0.0f;
    float mval = -1.0f;
    unsigned midx = 0u;

    #pragma unroll 4
    for (int st = 0; st < STAGES; st++) {
        cp_wait<DEPTH - 1>();                 // oldest group (this slot) done
        const int slot = st & (DEPTH - 1);
        const float4 t = sbuf[slot][0][tid];  // LDS.128, own bytes only
        const float4 o = sbuf[slot][1][tid];

        // refill this slot with stage st+DEPTH (WAR safe: same thread, LDS
        // already completed; cp.async write lands >=1 gmem latency later)
        const int nst = st + DEPTH;
        if (nst < STAGES) {
            cp16(st_addr[slot], tg + nst * STAGE_ELEMS + toff);
            cp16(so_addr[slot], og + nst * STAGE_ELEMS + toff);
        }
        cp_commit();                           // keep group accounting uniform

        const float d0 = o.x - t.x, d1 = o.y - t.y;
        const float d2 = o.z - t.z, d3 = o.w - t.w;
        s0 += d0 * d0 + d1 * d1;
        s1 += d2 * d2 + d3 * d3;

        const float m4 = vmax4(t);
        if (m4 > mval) {                       // rare after warmup
            mval = m4;
            midx = idx0 + (unsigned)(st * STAGE_ELEMS + toff) + vpick4(t, m4);
        }
    }
    float s = s0 + s1;

    unsigned long long bk =
        ((unsigned long long)__float_as_uint(mval) << 32) | (0xFFFFFFFFu - midx);

    #pragma unroll
    for (int off = 16; off > 0; off >>= 1) {
        s += __shfl_down_sync(0xFFFFFFFFu, s, off);
        unsigned long long ok = __shfl_down_sync(0xFFFFFFFFu, bk, off);
        if (ok > bk) bk = ok;
    }

    __shared__ float ssum[8];
    __shared__ unsigned long long skey[8];
    __shared__ int s_fix, s_last;
    const int w = tid >> 5, l = tid & 31;
    if (l == 0) { ssum[w] = s; skey[w] = bk; }
    __syncthreads();

    if (tid == 0) {
        float ts = 0.0f;
        unsigned long long tk = skey[0];
        #pragma unroll
        for (int i = 0; i < 8; i++) {
            ts += ssum[i];
            if (skey[i] > tk) tk = skey[i];
        }
        g_part1[blockIdx.x]  = (double)ts;
        g_keyblk[blockIdx.x] = tk;
        __threadfence();
        unsigned t = atomicAdd(&g_bdone[batch], 1u);
        s_fix = (t == BPB - 1) ? 1 : 0;
        if (s_fix) g_bdone[batch] = 0;         // reset for next graph replay
    }
    __syncthreads();

    // -------- phase B: per-batch window fix-up --------
    if (s_fix) {
        __threadfence();  // acquire: other chunks' g_keyblk stores visible
        unsigned long long key = g_keyblk[BPB * batch];
        #pragma unroll
        for (int j = 1; j < BPB; j++) {
            unsigned long long k = g_keyblk[BPB * batch + j];
            if (k > key) key = k;
        }
        const float mv = __uint_as_float((unsigned)(key >> 32));

        float fs = 0.0f;
        if (mv >= FWHM) {
            const unsigned pos = 0xFFFFFFFFu - (unsigned)(key & 0xFFFFFFFFu);
            const int ph = (int)(pos >> 9);
            const int pw = (int)(pos & 511u);
            const int top   = max(ph - DHW, 0);
            const int bot   = min(ph + DHW, NH);
            const int left  = max(pw - DHW, 0);
            const int right = min(pw + DHW, NW);
            const int Lh = bot - top, Lw = right - left;
            const float dh = (float)max((Lh + 1) / 2 - 1, 1);
            const float dw = (float)max((Lw + 1) / 2 - 1, 1);
            const size_t bbase = (size_t)batch << 18;

            const int c  = tid & 63;            // column within window
            const int r0 = tid >> 6;            // 4 row-lanes, stride 4
            if (c < Lw) {
                const float vw = 1.0f + 9.0f * (float)min(c, Lw - 1 - c) / dw;
                #pragma unroll
                for (int j = 0; j < 16; j++) {
                    const int r = r0 + 4 * j;
                    if (r < Lh) {
                        const float vh = 1.0f + 9.0f * (float)min(r, Lh - 1 - r) / dh;
                        const size_t idx = bbase + ((size_t)(top + r) << 9)
                                                 + (size_t)(left + c);
                        const float d = outp[idx] - tgtp[idx];
                        fs += d * d * (vh * vw - 1.0f);
                    }
                }
            }
        }

        #pragma unroll
        for (int off = 16; off > 0; off >>= 1)
            fs += __shfl_down_sync(0xFFFFFFFFu, fs, off);
        if (l == 0) ssum[w] = fs;
        __syncthreads();
        if (tid == 0) {
            float t2 = 0.0f;
            #pragma unroll
            for (int i = 0; i < 8; i++) t2 += ssum[i];
            g_part2[batch] = (double)t2;
        }
    }

    // ---------------- phase C: global last block finalizes ----------------
    if (tid == 0) {
        __threadfence();
        unsigned ticket = atomicAdd(&g_done, 1u);
        s_last = (ticket == NBLK - 1) ? 1 : 0;
        if (s_last) g_done = 0;                // reset for next graph replay
    }
    __syncthreads();

    if (s_last) {
        __threadfence();                        // all partials visible
        __shared__ double sh[256];
        double acc = g_part2[tid];
        #pragma unroll
        for (int j = 0; j < BPB; j++)
            acc += g_part1[tid + 256 * j];
        sh[tid] = acc;
        __syncthreads();
        #pragma unroll
        for (int stp = 128; stp > 0; stp >>= 1) {
            if (tid < stp) sh[tid] += sh[tid + stp];
            __syncthreads();
        }
        if (tid == 0)
            res[0] = (float)(sh[0] * (1.0 / (double)NTOT));
    }
}

extern "C" void kernel_launch(void* const* d_in, const int* in_sizes, int n_in,
                              void* d_out, int out_size) {
    const float* outp = (const float*)d_in[0];   // "output" (normal)
    const float* tgtp = (const float*)d_in[1];   // "target" (uniform)
    float* res = (float*)d_out;

    fused_kernel<<<NBLK, 256>>>(outp, tgtp, res);
}

// round 11
// speedup vs baseline: 1.0151x; 1.0151x over previous
#include <cuda_runtime.h>
#include <cuda_bf16.h>
#include <cstdint>

// Problem shape
#define NB   256
#define NH   512
#define NW   512
#define HW   (NH * NW)          // 262144 = 1<<18
#define NTOT ((size_t)NB * HW)  // 67108864
#define BPB  16                 // blocks per batch (fine-grained, ~9 waves)
#define NBLK (NB * BPB)         // 4096
#define CHUNK (HW / BPB)        // 16384 elems per block (64KB/array)
#define ITERS (CHUNK / 4 / 256) // 16 float4 slots per thread
#define FWHM 0.5f
#define DHW  32                 // h/H_SCALE = w/W_SCALE = 512/16

// Scratch (no allocations allowed — __device__ globals, zeroed at load)
__device__ unsigned long long g_keyblk[NBLK];  // per-block argmax key
__device__ double   g_part1[NBLK];             // per-block unweighted sqdiff sum
__device__ double   g_part2[NB];               // per-batch window correction
__device__ unsigned g_bdone[NB];               // per-batch ticket (self-resetting)
__device__ unsigned g_done;                    // global ticket  (self-resetting)

// max of a float4
__device__ __forceinline__ float vmax4(float4 v) {
    return fmaxf(fmaxf(v.x, v.y), fmaxf(v.z, v.w));
}
// first index (0..3) within float4 equal to m
__device__ __forceinline__ unsigned vpick4(float4 v, float m) {
    return (v.x == m) ? 0u : (v.y == m) ? 1u : (v.z == m) ? 2u : 3u;
}

// ---------------------------------------------------------------------------
// ONE fused kernel, fine-grained blocks + high-MLP streaming:
//  phase A: 8 front-batched evict-first LDG.128 per iteration (R8's winning
//     loop), but 4096 small blocks (~9 waves) so the completion-spread tail
//     is one SMALL block instead of spread x T_CTA(large).
//     Accumulate unweighted sum((o-t)^2) + per-block first-argmax of target.
//     key = (float_bits << 32) | (0xFFFFFFFF - idx): target in [0,1) so uint
//     order == float order; larger ~idx under max => first-max tie-break.
//  phase B (last block of each batch): <=64x64 ramp-window correction,
//     overlapped under later batches' streaming.
//  phase C (globally last block): deterministic sum of all partials -> mean.
// ---------------------------------------------------------------------------
__global__ __launch_bounds__(256)
void fused_kernel(const float* __restrict__ outp, const float* __restrict__ tgtp,
                  float* __restrict__ res) {
    const int batch = blockIdx.x >> 4;        // / BPB
    const int chunk = blockIdx.x & (BPB - 1);
    const size_t base = (size_t)batch * HW + (size_t)chunk * CHUNK;
    const float4* __restrict__ o4 = (const float4*)(outp + base);
    const float4* __restrict__ t4 = (const float4*)(tgtp + base);
    const unsigned idx0 = (unsigned)(chunk * CHUNK);
    const int tid = threadIdx.x;

    // ---------------- phase A: streaming, 8 batched loads / iter ----------------
    float s0 = 0.0f, s1 = 0.0f;
    float mval = -1.0f;
    unsigned midx = 0u;

    #pragma unroll 1
    for (int j = 0; j < ITERS; j += 4) {
        const int i0 = tid + j * 256;
        // 8 independent evict-first loads, front-batched (MLP)
        float4 ta = __ldcs(t4 + i0);
        float4 tb = __ldcs(t4 + i0 + 256);
        float4 tc = __ldcs(t4 + i0 + 512);
        float4 td = __ldcs(t4 + i0 + 768);
        float4 oa = __ldcs(o4 + i0);
        float4 ob = __ldcs(o4 + i0 + 256);
        float4 oc = __ldcs(o4 + i0 + 512);
        float4 od = __ldcs(o4 + i0 + 768);

        float a0 = oa.x - ta.x, a1 = oa.y - ta.y, a2 = oa.z - ta.z, a3 = oa.w - ta.w;
        float b0 = ob.x - tb.x, b1 = ob.y - tb.y, b2 = ob.z - tb.z, b3 = ob.w - tb.w;
        float c0 = oc.x - tc.x, c1 = oc.y - tc.y, c2 = oc.z - tc.z, c3 = oc.w - tc.w;
        float e0 = od.x - td.x, e1 = od.y - td.y, e2 = od.z - td.z, e3 = od.w - td.w;
        s0 += a0*a0 + a1*a1 + a2*a2 + a3*a3;
        s1 += b0*b0 + b1*b1 + b2*b2 + b3*b3;
        s0 += c0*c0 + c1*c1 + c2*c2 + c3*c3;
        s1 += e0*e0 + e1*e1 + e2*e2 + e3*e3;

        const float ma = vmax4(ta), mb = vmax4(tb), mc = vmax4(tc), md = vmax4(td);
        const float m16 = fmaxf(fmaxf(ma, mb), fmaxf(mc, md));
        if (m16 > mval) {                       // very rare
            mval = m16;
            const unsigned eb = idx0 + 4u * (unsigned)i0;
            if      (ma == m16) midx = eb +         vpick4(ta, m16);
            else if (mb == m16) midx = eb + 1024u + vpick4(tb, m16);
            else if (mc == m16) midx = eb + 2048u + vpick4(tc, m16);
            else                midx = eb + 3072u + vpick4(td, m16);
        }
    }
    float s = s0 + s1;

    unsigned long long bk =
        ((unsigned long long)__float_as_uint(mval) << 32) | (0xFFFFFFFFu - midx);

    #pragma unroll
    for (int off = 16; off > 0; off >>= 1) {
        s += __shfl_down_sync(0xFFFFFFFFu, s, off);
        unsigned long long ok = __shfl_down_sync(0xFFFFFFFFu, bk, off);
        if (ok > bk) bk = ok;
    }

    __shared__ float ssum[8];
    __shared__ unsigned long long skey[8];
    __shared__ int s_fix, s_last;
    const int w = tid >> 5, l = tid & 31;
    if (l == 0) { ssum[w] = s; skey[w] = bk; }
    __syncthreads();

    if (tid == 0) {
        float ts = 0.0f;
        unsigned long long tk = skey[0];
        #pragma unroll
        for (int i = 0; i < 8; i++) {
            ts += ssum[i];
            if (skey[i] > tk) tk = skey[i];
        }
        g_part1[blockIdx.x]  = (double)ts;
        g_keyblk[blockIdx.x] = tk;
        __threadfence();
        unsigned t = atomicAdd(&g_bdone[batch], 1u);
        s_fix = (t == BPB - 1) ? 1 : 0;
        if (s_fix) g_bdone[batch] = 0;         // reset for next graph replay
    }
    __syncthreads();

    // -------- phase B: per-batch window fix-up (overlaps later streaming) --------
    if (s_fix) {
        __threadfence();  // acquire: other chunks' g_keyblk stores visible
        unsigned long long key = g_keyblk[BPB * batch];
        #pragma unroll
        for (int j = 1; j < BPB; j++) {
            unsigned long long k = g_keyblk[BPB * batch + j];
            if (k > key) key = k;
        }
        const float mv = __uint_as_float((unsigned)(key >> 32));

        float fs = 0.0f;
        if (mv >= FWHM) {
            const unsigned pos = 0xFFFFFFFFu - (unsigned)(key & 0xFFFFFFFFu);
            const int ph = (int)(pos >> 9);
            const int pw = (int)(pos & 511u);
            const int top   = max(ph - DHW, 0);
            const int bot   = min(ph + DHW, NH);
            const int left  = max(pw - DHW, 0);
            const int right = min(pw + DHW, NW);
            const int Lh = bot - top, Lw = right - left;
            const float dh = (float)max((Lh + 1) / 2 - 1, 1);
            const float dw = (float)max((Lw + 1) / 2 - 1, 1);
            const size_t bbase = (size_t)batch << 18;

            const int c  = tid & 63;            // column within window
            const int r0 = tid >> 6;            // 4 row-lanes, stride 4
            if (c < Lw) {
                const float vw = 1.0f + 9.0f * (float)min(c, Lw - 1 - c) / dw;
                #pragma unroll
                for (int j = 0; j < 16; j++) {
                    const int r = r0 + 4 * j;
                    if (r < Lh) {
                        const float vh = 1.0f + 9.0f * (float)min(r, Lh - 1 - r) / dh;
                        const size_t idx = bbase + ((size_t)(top + r) << 9)
                                                 + (size_t)(left + c);
                        const float d = outp[idx] - tgtp[idx];
                        fs += d * d * (vh * vw - 1.0f);
                    }
                }
            }
        }

        #pragma unroll
        for (int off = 16; off > 0; off >>= 1)
            fs += __shfl_down_sync(0xFFFFFFFFu, fs, off);
        if (l == 0) ssum[w] = fs;
        __syncthreads();
        if (tid == 0) {
            float t2 = 0.0f;
            #pragma unroll
            for (int i = 0; i < 8; i++) t2 += ssum[i];
            g_part2[batch] = (double)t2;
        }
    }

    // ---------------- phase C: global last block finalizes ----------------
    if (tid == 0) {
        __threadfence();
        unsigned ticket = atomicAdd(&g_done, 1u);
        s_last = (ticket == NBLK - 1) ? 1 : 0;
        if (s_last) g_done = 0;                // reset for next graph replay
    }
    __syncthreads();

    if (s_last) {
        __threadfence();                        // all partials visible
        __shared__ double sh[256];
        double acc = g_part2[tid];
        #pragma unroll
        for (int j = 0; j < BPB; j++)
            acc += g_part1[tid + 256 * j];
        sh[tid] = acc;
        __syncthreads();
        #pragma unroll
        for (int st = 128; st > 0; st >>= 1) {
            if (tid < st) sh[tid] += sh[tid + st];
            __syncthreads();
        }
        if (tid == 0)
            res[0] = (float)(sh[0] * (1.0 / (double)NTOT));
    }
}

extern "C" void kernel_launch(void* const* d_in, const int* in_sizes, int n_in,
                              void* d_out, int out_size) {
    const float* outp = (const float*)d_in[0];   // "output" (normal)
    const float* tgtp = (const float*)d_in[1];   // "target" (uniform)
    float* res = (float*)d_out;

    fused_kernel<<<NBLK, 256>>>(outp, tgtp, res);
}

// round 12
// speedup vs baseline: 1.1235x; 1.1068x over previous
#include <cuda_runtime.h>
#include <cuda_bf16.h>
#include <cstdint>

// Problem shape
#define NB   256
#define NH   512
#define NW   512
#define HW   (NH * NW)          // 262144 = 1<<18
#define NTOT ((size_t)NB * HW)  // 67108864
#define BPB  4                  // blocks per batch in pass 1
#define NBLK (NB * BPB)         // 1024
#define CHUNK (HW / BPB)        // 65536 elems per block
#define ITERS (CHUNK / 4 / 256) // 64 float4 slots per thread
#define P2BLKS (NB * 4)         // 1024 pass-2 blocks (4 per batch)
#define FWHM 0.5f
#define DHW  32                 // h/H_SCALE = w/W_SCALE = 512/16

// Scratch (no allocations allowed — __device__ globals, zeroed at load)
__device__ unsigned long long g_keyblk[NBLK];  // per-block argmax key
__device__ double   g_part1[NBLK];             // per-block unweighted sqdiff sum
__device__ double   g_part2[P2BLKS];           // per-pass2-block window correction
__device__ unsigned g_done;                    // global ticket (self-resetting)

// max of a float4
__device__ __forceinline__ float vmax4(float4 v) {
    return fmaxf(fmaxf(v.x, v.y), fmaxf(v.z, v.w));
}
// first index (0..3) within float4 equal to m
__device__ __forceinline__ unsigned vpick4(float4 v, float m) {
    return (v.x == m) ? 0u : (v.y == m) ? 1u : (v.z == m) ? 2u : 3u;
}

// ---------------------------------------------------------------------------
// Pass 1: PURE streaming — 8 front-batched evict-first LDG.128 per iteration,
// zero epilogue baggage (no fences/atomics/fix-up code in this kernel).
// Accumulates unweighted sum((o-t)^2) + per-block first-argmax of target.
//   key = (float_bits << 32) | (0xFFFFFFFF - idx): target in [0,1) so uint
//   order == float order; larger ~idx under max => first-max tie-break.
// ---------------------------------------------------------------------------
__global__ __launch_bounds__(256, 4)
void pass1_kernel(const float* __restrict__ outp, const float* __restrict__ tgtp) {
    const int batch = blockIdx.x >> 2;        // / BPB
    const int chunk = blockIdx.x & (BPB - 1);
    const size_t base = (size_t)batch * HW + (size_t)chunk * CHUNK;
    const float4* __restrict__ o4 = (const float4*)(outp + base);
    const float4* __restrict__ t4 = (const float4*)(tgtp + base);
    const unsigned idx0 = (unsigned)(chunk * CHUNK);
    const int tid = threadIdx.x;

    float s0 = 0.0f, s1 = 0.0f;
    float mval = -1.0f;
    unsigned midx = 0u;

    #pragma unroll 1
    for (int j = 0; j < ITERS; j += 4) {
        const int i0 = tid + j * 256;
        // 8 independent evict-first loads, front-batched (MLP)
        float4 ta = __ldcs(t4 + i0);
        float4 tb = __ldcs(t4 + i0 + 256);
        float4 tc = __ldcs(t4 + i0 + 512);
        float4 td = __ldcs(t4 + i0 + 768);
        float4 oa = __ldcs(o4 + i0);
        float4 ob = __ldcs(o4 + i0 + 256);
        float4 oc = __ldcs(o4 + i0 + 512);
        float4 od = __ldcs(o4 + i0 + 768);

        float a0 = oa.x - ta.x, a1 = oa.y - ta.y, a2 = oa.z - ta.z, a3 = oa.w - ta.w;
        float b0 = ob.x - tb.x, b1 = ob.y - tb.y, b2 = ob.z - tb.z, b3 = ob.w - tb.w;
        float c0 = oc.x - tc.x, c1 = oc.y - tc.y, c2 = oc.z - tc.z, c3 = oc.w - tc.w;
        float e0 = od.x - td.x, e1 = od.y - td.y, e2 = od.z - td.z, e3 = od.w - td.w;
        s0 += a0*a0 + a1*a1 + a2*a2 + a3*a3;
        s1 += b0*b0 + b1*b1 + b2*b2 + b3*b3;
        s0 += c0*c0 + c1*c1 + c2*c2 + c3*c3;
        s1 += e0*e0 + e1*e1 + e2*e2 + e3*e3;

        const float ma = vmax4(ta), mb = vmax4(tb), mc = vmax4(tc), md = vmax4(td);
        const float m16 = fmaxf(fmaxf(ma, mb), fmaxf(mc, md));
        if (m16 > mval) {                       // very rare
            mval = m16;
            const unsigned eb = idx0 + 4u * (unsigned)i0;
            if      (ma == m16) midx = eb +         vpick4(ta, m16);
            else if (mb == m16) midx = eb + 1024u + vpick4(tb, m16);
            else if (mc == m16) midx = eb + 2048u + vpick4(tc, m16);
            else                midx = eb + 3072u + vpick4(td, m16);
        }
    }
    float s = s0 + s1;

    unsigned long long bk =
        ((unsigned long long)__float_as_uint(mval) << 32) | (0xFFFFFFFFu - midx);

    #pragma unroll
    for (int off = 16; off > 0; off >>= 1) {
        s += __shfl_down_sync(0xFFFFFFFFu, s, off);
        unsigned long long ok = __shfl_down_sync(0xFFFFFFFFu, bk, off);
        if (ok > bk) bk = ok;
    }

    __shared__ float ssum[8];
    __shared__ unsigned long long skey[8];
    const int w = tid >> 5, l = tid & 31;
    if (l == 0) { ssum[w] = s; skey[w] = bk; }
    __syncthreads();

    if (tid == 0) {
        float ts = 0.0f;
        unsigned long long tk = skey[0];
        #pragma unroll
        for (int i = 0; i < 8; i++) {
            ts += ssum[i];
            if (skey[i] > tk) tk = skey[i];
        }
        g_part1[blockIdx.x]  = (double)ts;
        g_keyblk[blockIdx.x] = tk;
    }
}

// ---------------------------------------------------------------------------
// Pass 2: window fix-up, 4 blocks per batch (16 window-rows each), vectorized
// parallel loads (one DRAM round-trip of latency). Last block (global ticket)
// does the deterministic final reduction + mean.
// ---------------------------------------------------------------------------
__global__ __launch_bounds__(256)
void pass2_kernel(const float* __restrict__ outp, const float* __restrict__ tgtp,
                  float* __restrict__ res) {
    const int b   = blockIdx.x >> 2;
    const int sub = blockIdx.x & 3;
    const int tid = threadIdx.x;

    // reduce this batch's 4 pass-1 keys
    unsigned long long key = g_keyblk[4 * b];
    #pragma unroll
    for (int j = 1; j < 4; j++) {
        unsigned long long k = g_keyblk[4 * b + j];
        if (k > key) key = k;
    }
    const float mv = __uint_as_float((unsigned)(key >> 32));

    float fs = 0.0f;
    if (mv >= FWHM) {
        const unsigned pos = 0xFFFFFFFFu - (unsigned)(key & 0xFFFFFFFFu);
        const int ph = (int)(pos >> 9);
        const int pw = (int)(pos & 511u);
        const int top   = max(ph - DHW, 0);
        const int bot   = min(ph + DHW, NH);
        const int left  = max(pw - DHW, 0);
        const int right = min(pw + DHW, NW);
        const int Lh = bot - top, Lw = right - left;
        const float dh = (float)max((Lh + 1) / 2 - 1, 1);
        const float dw = (float)max((Lw + 1) / 2 - 1, 1);
        const size_t bbase = (size_t)b << 18;

        const int r = sub * 16 + (tid >> 4);   // window row 0..63
        const int q = tid & 15;                // 4-col group 0..15
        if (r < Lh) {
            const float vh = 1.0f + 9.0f * (float)min(r, Lh - 1 - r) / dh;
            const size_t rowbase = bbase + ((size_t)(top + r) << 9) + (size_t)left;
            #pragma unroll
            for (int k = 0; k < 4; k++) {
                const int c = q * 4 + k;
                if (c < Lw) {
                    const float vw = 1.0f + 9.0f * (float)min(c, Lw - 1 - c) / dw;
                    const float d = outp[rowbase + c] - tgtp[rowbase + c];
                    fs += d * d * (vh * vw - 1.0f);
                }
            }
        }
    }

    // block reduce (fixed order => deterministic)
    #pragma unroll
    for (int off = 16; off > 0; off >>= 1)
        fs += __shfl_down_sync(0xFFFFFFFFu, fs, off);
    __shared__ float ssum[8];
    __shared__ int s_last;
    const int w = tid >> 5, l = tid & 31;
    if (l == 0) ssum[w] = fs;
    __syncthreads();
    if (tid == 0) {
        float t2 = 0.0f;
        #pragma unroll
        for (int i = 0; i < 8; i++) t2 += ssum[i];
        g_part2[blockIdx.x] = (double)t2;
        __threadfence();
        unsigned ticket = atomicAdd(&g_done, 1u);
        s_last = (ticket == P2BLKS - 1) ? 1 : 0;
        if (s_last) g_done = 0;                // reset for next graph replay
    }
    __syncthreads();

    // Globally last block: deterministic final reduction + mean.
    if (s_last) {
        __threadfence();                        // all partials visible
        __shared__ double sh[256];
        double acc = 0.0;
        #pragma unroll
        for (int j = 0; j < 4; j++) {
            acc += g_part1[tid + 256 * j];
            acc += g_part2[tid + 256 * j];
        }
        sh[tid] = acc;
        __syncthreads();
        #pragma unroll
        for (int st = 128; st > 0; st >>= 1) {
            if (tid < st) sh[tid] += sh[tid + st];
            __syncthreads();
        }
        if (tid == 0)
            res[0] = (float)(sh[0] * (1.0 / (double)NTOT));
    }
}

extern "C" void kernel_launch(void* const* d_in, const int* in_sizes, int n_in,
                              void* d_out, int out_size) {
    const float* outp = (const float*)d_in[0];   // "output" (normal)
    const float* tgtp = (const float*)d_in[1];   // "target" (uniform)
    float* res = (float*)d_out;

    pass1_kernel<<<NBLK, 256>>>(outp, tgtp);
    pass2_kernel<<<P2BLKS, 256>>>(outp, tgtp, res);
}